// round 1
// baseline (speedup 1.0000x reference)
#include <cuda_runtime.h>
#include <cuda_bf16.h>

#define NN 50000
#define NE 1600000
#define INF 128
#define UNITS 64
#define OUTF 40
#define NL 6
#define HCATW (NL * UNITS)   // 384

// Scratch (device globals: no allocation allowed)
__device__ float g_ylin[NN * UNITS];          // h @ w_lin
__device__ float g_hpre[NN * UNITS];          // accumulator: h@w_self + biases, then += segsum
__device__ float g_hcat[NN * HCATW];          // relu'd outputs of all layers (also next-layer input)

// ----------------------------------------------------------------------------
// Dual GEMM: ylin = in @ wl ;  hpre = in @ ws + (bl + bs + bias)
// in: [NN, K] with row stride in_stride. Block = 64 rows, blockDim (64,4).
// ----------------------------------------------------------------------------
template <int K>
__global__ void gemm_dual(const float* __restrict__ in, int in_stride,
                          const float* __restrict__ wl, const float* __restrict__ ws,
                          const float* __restrict__ bl, const float* __restrict__ bs,
                          const float* __restrict__ bias)
{
    extern __shared__ float sm[];
    float* sh_wl = sm;                 // K*64
    float* sh_ws = sm + K * 64;        // K*64
    float* sh_h  = sm + 2 * K * 64;    // 64*K

    const int tid = threadIdx.y * 64 + threadIdx.x;   // 0..255
    for (int i = tid; i < K * 64; i += 256) {
        sh_wl[i] = wl[i];
        sh_ws[i] = ws[i];
    }
    const int row0 = blockIdx.x * 64;
    for (int i = tid; i < 64 * K; i += 256) {
        int r = i / K, k = i - r * K;
        int gr = row0 + r;
        sh_h[i] = (gr < NN) ? in[(long long)gr * in_stride + k] : 0.f;
    }
    __syncthreads();

    const int c = threadIdx.x;         // output column 0..63
    const float btot = bl[c] + bs[c] + bias[c];

    for (int r = threadIdx.y; r < 64; r += 4) {
        const int gr = row0 + r;
        if (gr >= NN) break;
        float accl = 0.f, accs = 0.f;
        const float* hrow = &sh_h[r * K];
#pragma unroll 16
        for (int k = 0; k < K; k++) {
            const float h = hrow[k];
            accl += h * sh_wl[k * 64 + c];
            accs += h * sh_ws[k * 64 + c];
        }
        g_ylin[gr * 64 + c] = accl;
        g_hpre[gr * 64 + c] = accs + btot;
    }
}

// ----------------------------------------------------------------------------
// Edge scatter: for each edge e: hpre[dst[e], :] += ylin[src[e], :]
// 16 threads per edge, one float4 + one red.global.add.v4.f32 each.
// ----------------------------------------------------------------------------
__global__ void scatter_add(const int* __restrict__ src, const int* __restrict__ dst)
{
    const unsigned idx = blockIdx.x * 256u + threadIdx.x;
    const unsigned e = idx >> 4;
    const unsigned q = idx & 15u;
    if (e >= NE) return;
    const int s = __ldg(&src[e]);
    const int d = __ldg(&dst[e]);
    const float4 v = *reinterpret_cast<const float4*>(&g_ylin[s * 64 + q * 4]);
    float* p = &g_hpre[d * 64 + q * 4];
    asm volatile("red.global.add.v4.f32 [%0], {%1, %2, %3, %4};"
                 :: "l"(p), "f"(v.x), "f"(v.y), "f"(v.z), "f"(v.w)
                 : "memory");
}

// ----------------------------------------------------------------------------
// relu + store into hcat slice for layer `layer`
// ----------------------------------------------------------------------------
__global__ void relu_store(int layer)
{
    const int i = blockIdx.x * 256 + threadIdx.x;
    if (i >= NN * UNITS) return;
    const int r = i >> 6;
    const int c = i & 63;
    const float v = g_hpre[i];
    g_hcat[r * HCATW + layer * UNITS + c] = v > 0.f ? v : 0.f;
}

// ----------------------------------------------------------------------------
// Final: out = hcat @ w_last + b_last   [NN,384]@[384,40]
// Block = 64 rows, blockDim (64,4); tx>=40 help load, idle in compute.
// ----------------------------------------------------------------------------
__global__ void gemm_last(const float* __restrict__ w, const float* __restrict__ b,
                          float* __restrict__ out)
{
    extern __shared__ float sm[];
    float* sh_w = sm;                  // 384*40
    float* sh_h = sm + HCATW * OUTF;   // 64*384

    const int tid = threadIdx.y * 64 + threadIdx.x;
    for (int i = tid; i < HCATW * OUTF; i += 256) sh_w[i] = w[i];
    const int row0 = blockIdx.x * 64;
    for (int i = tid; i < 64 * HCATW; i += 256) {
        int r = i / HCATW, k = i - r * HCATW;
        int gr = row0 + r;
        sh_h[i] = (gr < NN) ? g_hcat[(long long)gr * HCATW + k] : 0.f;
    }
    __syncthreads();

    const int c = threadIdx.x;
    if (c >= OUTF) return;
    const float bc = b[c];
    for (int r = threadIdx.y; r < 64; r += 4) {
        const int gr = row0 + r;
        if (gr >= NN) break;
        float acc = bc;
        const float* hrow = &sh_h[r * HCATW];
#pragma unroll 8
        for (int k = 0; k < HCATW; k++)
            acc += hrow[k] * sh_w[k * OUTF + c];
        out[gr * OUTF + c] = acc;
    }
}

// ----------------------------------------------------------------------------
extern "C" void kernel_launch(void* const* d_in, const int* in_sizes, int n_in,
                              void* d_out, int out_size)
{
    const float* x      = (const float*)d_in[0];
    const int*   src    = (const int*)  d_in[1];
    const int*   dst    = (const int*)  d_in[2];
    const float* w0l    = (const float*)d_in[3];
    const float* b0l    = (const float*)d_in[4];
    const float* w0s    = (const float*)d_in[5];
    const float* b0s    = (const float*)d_in[6];
    const float* bias0  = (const float*)d_in[7];
    const float* w_lin  = (const float*)d_in[8];   // [5,64,64]
    const float* b_lin  = (const float*)d_in[9];   // [5,64]
    const float* w_self = (const float*)d_in[10];  // [5,64,64]
    const float* b_self = (const float*)d_in[11];  // [5,64]
    const float* bias   = (const float*)d_in[12];  // [5,64]
    const float* w_last = (const float*)d_in[13];  // [384,40]
    const float* b_last = (const float*)d_in[14];  // [40]
    float* out = (float*)d_out;

    const int SMEM0 = (2 * INF * 64 + 64 * INF) * 4;           // 98304
    const int SMEM1 = (2 * 64 * 64 + 64 * 64) * 4;             // 49152
    const int SMEML = (HCATW * OUTF + 64 * HCATW) * 4;         // 159744

    cudaFuncSetAttribute((const void*)gemm_dual<INF>,
                         cudaFuncAttributeMaxDynamicSharedMemorySize, SMEM0);
    cudaFuncSetAttribute((const void*)gemm_dual<64>,
                         cudaFuncAttributeMaxDynamicSharedMemorySize, SMEM1);
    cudaFuncSetAttribute((const void*)gemm_last,
                         cudaFuncAttributeMaxDynamicSharedMemorySize, SMEML);

    void* hcat_p = nullptr;
    cudaGetSymbolAddress(&hcat_p, g_hcat);
    const float* hcat = (const float*)hcat_p;

    const dim3 gb(64, 4);
    const int nblk = (NN + 63) / 64;                           // 782
    const int scat_blk = (NE * 16 + 255) / 256;                // 100000
    const int relu_blk = (NN * UNITS + 255) / 256;

    // Layer 0 (input x, K=128)
    gemm_dual<INF><<<nblk, gb, SMEM0>>>(x, INF, w0l, w0s, b0l, b0s, bias0);
    scatter_add<<<scat_blk, 256>>>(src, dst);
    relu_store<<<relu_blk, 256>>>(0);

    // Layers 1..5 (input = previous hcat slice, stride 384)
    for (int l = 1; l < NL; l++) {
        const float* in = hcat + (l - 1) * UNITS;
        const float* wl = w_lin  + (l - 1) * 64 * 64;
        const float* bl = b_lin  + (l - 1) * 64;
        const float* ws = w_self + (l - 1) * 64 * 64;
        const float* bs = b_self + (l - 1) * 64;
        const float* bi = bias   + (l - 1) * 64;
        gemm_dual<64><<<nblk, gb, SMEM1>>>(in, HCATW, wl, ws, bl, bs, bi);
        scatter_add<<<scat_blk, 256>>>(src, dst);
        relu_store<<<relu_blk, 256>>>(l);
    }

    // Final projection
    gemm_last<<<nblk, gb, SMEML>>>(w_last, b_last, out);
}

// round 2
// speedup vs baseline: 2.2805x; 2.2805x over previous
#include <cuda_runtime.h>
#include <cuda_bf16.h>

#define NN 50000
#define NE 1600000
#define INF 128
#define UNITS 64
#define OUTF 40
#define NL 6
#define HCATW (NL * UNITS)   // 384

// ---- device-global scratch (no allocation allowed) ----
__device__ float g_ylin[NN * UNITS];        // h @ w_lin (gather source)
__device__ float g_hpre[NN * UNITS];        // h @ w_self + (bl+bs+bias)
__device__ float g_hcat[NN * HCATW];        // relu'd layer outputs (also next-layer input)
__device__ int   g_deg[NN];
__device__ int   g_rowptr[NN + 1];
__device__ int   g_cursor[NN];
__device__ int   g_csr_src[NE];

// ============================================================================
// CSR build
// ============================================================================
__global__ void zero_deg()
{
    int i = blockIdx.x * 256 + threadIdx.x;
    if (i < NN) g_deg[i] = 0;
}

__global__ void hist_deg(const int* __restrict__ dst)
{
    int e = blockIdx.x * 256 + threadIdx.x;
    if (e < NE) atomicAdd(&g_deg[dst[e]], 1);
}

__global__ void scan_csr()   // 1 block, 1024 threads
{
    __shared__ int sums[1024];
    const int CH = (NN + 1023) / 1024;   // 49
    const int t = threadIdx.x;
    const int base = t * CH;
    int s = 0;
    for (int i = 0; i < CH; i++) {
        int idx = base + i;
        if (idx < NN) s += g_deg[idx];
    }
    sums[t] = s;
    __syncthreads();
    // Hillis-Steele inclusive scan
    for (int off = 1; off < 1024; off <<= 1) {
        int v = (t >= off) ? sums[t - off] : 0;
        __syncthreads();
        sums[t] += v;
        __syncthreads();
    }
    int run = sums[t] - s;               // exclusive prefix of this chunk
    for (int i = 0; i < CH; i++) {
        int idx = base + i;
        if (idx < NN) {
            g_rowptr[idx] = run;
            g_cursor[idx] = run;
            run += g_deg[idx];
        }
    }
    if (t == 1023) g_rowptr[NN] = sums[1023];
}

__global__ void fill_csr(const int* __restrict__ src, const int* __restrict__ dst)
{
    int e = blockIdx.x * 256 + threadIdx.x;
    if (e >= NE) return;
    int pos = atomicAdd(&g_cursor[dst[e]], 1);
    g_csr_src[pos] = src[e];
}

// ============================================================================
// Dual GEMM, 4x4 register tile:
//   g_ylin = in @ wl ;  g_hpre = in @ ws + (bl + bs + bias)
// blockDim 256 (16x16 thread tile), 64 rows per block.
// ============================================================================
template <int K>
__global__ void gemm_dual(const float* __restrict__ in, int in_stride,
                          const float* __restrict__ wl, const float* __restrict__ ws,
                          const float* __restrict__ bl, const float* __restrict__ bs,
                          const float* __restrict__ bias)
{
    extern __shared__ float sm[];
    float* sh_wl = sm;                 // [K][64]
    float* sh_ws = sm + K * 64;        // [K][64]
    float* sh_h  = sm + 2 * K * 64;    // [64][K]

    const int tid = threadIdx.x;
    for (int i = tid; i < K * 16; i += 256) {           // K*64/4 float4s
        ((float4*)sh_wl)[i] = ((const float4*)wl)[i];
        ((float4*)sh_ws)[i] = ((const float4*)ws)[i];
    }
    const int row0 = blockIdx.x * 64;
    for (int i = tid; i < 64 * (K / 4); i += 256) {
        int r = i / (K / 4), kq = i % (K / 4);
        int gr = row0 + r;
        float4 v = make_float4(0.f, 0.f, 0.f, 0.f);
        if (gr < NN) v = ((const float4*)(in + (size_t)gr * in_stride))[kq];
        ((float4*)(sh_h + r * K))[kq] = v;
    }
    __syncthreads();

    const int tx = tid & 15, ty = tid >> 4;
    const int c0 = tx * 4, r0 = ty * 4;

    float accl[4][4] = {}, accs[4][4] = {};
#pragma unroll 8
    for (int k = 0; k < K; k++) {
        const float4 wlv = ((const float4*)(sh_wl + k * 64))[tx];
        const float4 wsv = ((const float4*)(sh_ws + k * 64))[tx];
        float h[4];
#pragma unroll
        for (int j = 0; j < 4; j++) h[j] = sh_h[(r0 + j) * K + k];
#pragma unroll
        for (int j = 0; j < 4; j++) {
            accl[j][0] += h[j] * wlv.x; accl[j][1] += h[j] * wlv.y;
            accl[j][2] += h[j] * wlv.z; accl[j][3] += h[j] * wlv.w;
            accs[j][0] += h[j] * wsv.x; accs[j][1] += h[j] * wsv.y;
            accs[j][2] += h[j] * wsv.z; accs[j][3] += h[j] * wsv.w;
        }
    }

    float4 bt;
    bt.x = bl[c0+0] + bs[c0+0] + bias[c0+0];
    bt.y = bl[c0+1] + bs[c0+1] + bias[c0+1];
    bt.z = bl[c0+2] + bs[c0+2] + bias[c0+2];
    bt.w = bl[c0+3] + bs[c0+3] + bias[c0+3];

#pragma unroll
    for (int j = 0; j < 4; j++) {
        int gr = row0 + r0 + j;
        if (gr < NN) {
            float4 yl = make_float4(accl[j][0], accl[j][1], accl[j][2], accl[j][3]);
            float4 hp = make_float4(accs[j][0] + bt.x, accs[j][1] + bt.y,
                                    accs[j][2] + bt.z, accs[j][3] + bt.w);
            ((float4*)(g_ylin + gr * 64))[tx] = yl;
            ((float4*)(g_hpre + gr * 64))[tx] = hp;
        }
    }
}

// ============================================================================
// Gather aggregation + relu + store into hcat slice.
// 16 threads per node (q = float4 column). No atomics.
// ============================================================================
__global__ void gather_relu(int layer)
{
    const int t = blockIdx.x * 256 + threadIdx.x;
    const int v = t >> 4;
    const int q = t & 15;
    if (v >= NN) return;
    const int beg = g_rowptr[v];
    const int end = g_rowptr[v + 1];

    float4 acc = make_float4(0.f, 0.f, 0.f, 0.f);
    int s = (beg < end) ? g_csr_src[beg] : 0;
    for (int e = beg; e < end; e++) {
        int snext = (e + 1 < end) ? g_csr_src[e + 1] : 0;
        float4 x = *(const float4*)(g_ylin + s * 64 + q * 4);
        acc.x += x.x; acc.y += x.y; acc.z += x.z; acc.w += x.w;
        s = snext;
    }
    const float4 hp = *(const float4*)(g_hpre + v * 64 + q * 4);
    float4 o;
    o.x = fmaxf(hp.x + acc.x, 0.f);
    o.y = fmaxf(hp.y + acc.y, 0.f);
    o.z = fmaxf(hp.z + acc.z, 0.f);
    o.w = fmaxf(hp.w + acc.w, 0.f);
    *(float4*)(g_hcat + (size_t)v * HCATW + layer * UNITS + q * 4) = o;
}

// ============================================================================
// Final: out = hcat @ w_last + b_last   [NN,384] @ [384,40]
// blockDim 160 (10 col-groups x 16 row-groups), 4x4 tile, K tiled by 64.
// ============================================================================
__global__ void gemm_last(const float* __restrict__ w, const float* __restrict__ b,
                          float* __restrict__ out)
{
    extern __shared__ float sm[];
    float* sh_w = sm;                  // [384][40]
    float* sh_h = sm + HCATW * OUTF;   // [64][64]

    const int tid = threadIdx.x;       // 0..159
    for (int i = tid; i < HCATW * OUTF / 4; i += 160)
        ((float4*)sh_w)[i] = ((const float4*)w)[i];

    const int row0 = blockIdx.x * 64;
    const int tx = tid % 10, ty = tid / 10;
    const int c0 = tx * 4, r0 = ty * 4;
    float acc[4][4] = {};

    for (int kt = 0; kt < HCATW / 64; kt++) {
        __syncthreads();
        for (int i = tid; i < 64 * 16; i += 160) {
            int r = i / 16, kq = i % 16;
            int gr = row0 + r;
            float4 v = make_float4(0.f, 0.f, 0.f, 0.f);
            if (gr < NN) v = *(const float4*)(g_hcat + (size_t)gr * HCATW + kt * 64 + kq * 4);
            ((float4*)(sh_h + r * 64))[kq] = v;
        }
        __syncthreads();
#pragma unroll 8
        for (int kk = 0; kk < 64; kk++) {
            const int k = kt * 64 + kk;
            const float4 wv = ((const float4*)(sh_w + k * OUTF))[tx];
            float h[4];
#pragma unroll
            for (int j = 0; j < 4; j++) h[j] = sh_h[(r0 + j) * 64 + kk];
#pragma unroll
            for (int j = 0; j < 4; j++) {
                acc[j][0] += h[j] * wv.x; acc[j][1] += h[j] * wv.y;
                acc[j][2] += h[j] * wv.z; acc[j][3] += h[j] * wv.w;
            }
        }
    }

    float4 bv = *(const float4*)(b + c0);
#pragma unroll
    for (int j = 0; j < 4; j++) {
        int gr = row0 + r0 + j;
        if (gr < NN) {
            float4 o = make_float4(acc[j][0] + bv.x, acc[j][1] + bv.y,
                                   acc[j][2] + bv.z, acc[j][3] + bv.w);
            *(float4*)(out + (size_t)gr * OUTF + c0) = o;
        }
    }
}

// ============================================================================
extern "C" void kernel_launch(void* const* d_in, const int* in_sizes, int n_in,
                              void* d_out, int out_size)
{
    const float* x      = (const float*)d_in[0];
    const int*   src    = (const int*)  d_in[1];
    const int*   dst    = (const int*)  d_in[2];
    const float* w0l    = (const float*)d_in[3];
    const float* b0l    = (const float*)d_in[4];
    const float* w0s    = (const float*)d_in[5];
    const float* b0s    = (const float*)d_in[6];
    const float* bias0  = (const float*)d_in[7];
    const float* w_lin  = (const float*)d_in[8];
    const float* b_lin  = (const float*)d_in[9];
    const float* w_self = (const float*)d_in[10];
    const float* b_self = (const float*)d_in[11];
    const float* bias   = (const float*)d_in[12];
    const float* w_last = (const float*)d_in[13];
    const float* b_last = (const float*)d_in[14];
    float* out = (float*)d_out;

    const int SMEM0 = (2 * INF * 64 + 64 * INF) * 4;            // 98304
    const int SMEM1 = (2 * 64 * 64 + 64 * 64) * 4;              // 49152
    const int SMEML = (HCATW * OUTF + 64 * 64) * 4;             // 77824

    cudaFuncSetAttribute((const void*)gemm_dual<INF>,
                         cudaFuncAttributeMaxDynamicSharedMemorySize, SMEM0);
    cudaFuncSetAttribute((const void*)gemm_dual<64>,
                         cudaFuncAttributeMaxDynamicSharedMemorySize, SMEM1);
    cudaFuncSetAttribute((const void*)gemm_last,
                         cudaFuncAttributeMaxDynamicSharedMemorySize, SMEML);

    void* hcat_p = nullptr;
    cudaGetSymbolAddress(&hcat_p, g_hcat);
    const float* hcat = (const float*)hcat_p;

    const int nblk     = (NN + 63) / 64;            // 782
    const int eblk     = (NE + 255) / 256;          // 6250
    const int nodeblk  = (NN + 255) / 256;          // 196
    const int gathblk  = (NN * 16 + 255) / 256;     // 3125

    // ---- CSR build (once per launch) ----
    zero_deg<<<nodeblk, 256>>>();
    hist_deg<<<eblk, 256>>>(dst);
    scan_csr<<<1, 1024>>>();
    fill_csr<<<eblk, 256>>>(src, dst);

    // ---- Layer 0 (input x, K=128) ----
    gemm_dual<INF><<<nblk, 256, SMEM0>>>(x, INF, w0l, w0s, b0l, b0s, bias0);
    gather_relu<<<gathblk, 256>>>(0);

    // ---- Layers 1..5 ----
    for (int l = 1; l < NL; l++) {
        const float* in = hcat + (l - 1) * UNITS;
        const float* wl = w_lin  + (l - 1) * 64 * 64;
        const float* bl = b_lin  + (l - 1) * 64;
        const float* ws = w_self + (l - 1) * 64 * 64;
        const float* bs = b_self + (l - 1) * 64;
        const float* bi = bias   + (l - 1) * 64;
        gemm_dual<64><<<nblk, 256, SMEM1>>>(in, HCATW, wl, bl ? ws : ws, bl, bs, bi);
        gather_relu<<<gathblk, 256>>>(l);
    }

    // ---- Final projection ----
    gemm_last<<<nblk, 160, SMEML>>>(w_last, b_last, out);
}

// round 3
// speedup vs baseline: 2.4568x; 1.0773x over previous
#include <cuda_runtime.h>
#include <cuda_fp16.h>
#include <cuda_bf16.h>

#define NN 50000
#define NE 1600000
#define INF 128
#define UNITS 64
#define OUTF 40
#define NL 6
#define HCATW (NL * UNITS)   // 384

// ---- device-global scratch (no allocation allowed) ----
__device__ __half g_ylin_h[NN * UNITS];     // h @ w_lin in fp16 (gather source)
__device__ float  g_hpre[NN * UNITS];       // h @ w_self + (bl+bs+bias), fp32
__device__ float  g_hcat[NN * HCATW];       // relu'd layer outputs (also next-layer input)
__device__ int    g_deg[NN];
__device__ int    g_rowptr[NN + 1];
__device__ int    g_cursor[NN];
__device__ int    g_csr_src[NE];

// ============================================================================
// CSR build
// ============================================================================
__global__ void zero_deg()
{
    int i = blockIdx.x * 256 + threadIdx.x;
    if (i < NN) g_deg[i] = 0;
}

__global__ void hist_deg(const int* __restrict__ dst)
{
    int e = blockIdx.x * 256 + threadIdx.x;
    if (e < NE) atomicAdd(&g_deg[dst[e]], 1);
}

__global__ void scan_csr()   // 1 block, 1024 threads
{
    __shared__ int sums[1024];
    const int CH = (NN + 1023) / 1024;   // 49
    const int t = threadIdx.x;
    const int base = t * CH;
    int s = 0;
    for (int i = 0; i < CH; i++) {
        int idx = base + i;
        if (idx < NN) s += g_deg[idx];
    }
    sums[t] = s;
    __syncthreads();
    for (int off = 1; off < 1024; off <<= 1) {
        int v = (t >= off) ? sums[t - off] : 0;
        __syncthreads();
        sums[t] += v;
        __syncthreads();
    }
    int run = sums[t] - s;
    for (int i = 0; i < CH; i++) {
        int idx = base + i;
        if (idx < NN) {
            g_rowptr[idx] = run;
            g_cursor[idx] = run;
            run += g_deg[idx];
        }
    }
    if (t == 1023) g_rowptr[NN] = sums[1023];
}

__global__ void fill_csr(const int* __restrict__ src, const int* __restrict__ dst)
{
    int e = blockIdx.x * 256 + threadIdx.x;
    if (e >= NE) return;
    int pos = atomicAdd(&g_cursor[dst[e]], 1);
    g_csr_src[pos] = src[e];
}

// ============================================================================
// Dual GEMM, 4x4 register tile:
//   g_ylin_h = fp16(in @ wl) ;  g_hpre = in @ ws + (bl + bs + bias)
// ============================================================================
template <int K>
__global__ void gemm_dual(const float* __restrict__ in, int in_stride,
                          const float* __restrict__ wl, const float* __restrict__ ws,
                          const float* __restrict__ bl, const float* __restrict__ bs,
                          const float* __restrict__ bias)
{
    extern __shared__ float sm[];
    float* sh_wl = sm;                 // [K][64]
    float* sh_ws = sm + K * 64;        // [K][64]
    float* sh_h  = sm + 2 * K * 64;    // [64][K]

    const int tid = threadIdx.x;
    for (int i = tid; i < K * 16; i += 256) {
        ((float4*)sh_wl)[i] = ((const float4*)wl)[i];
        ((float4*)sh_ws)[i] = ((const float4*)ws)[i];
    }
    const int row0 = blockIdx.x * 64;
    for (int i = tid; i < 64 * (K / 4); i += 256) {
        int r = i / (K / 4), kq = i % (K / 4);
        int gr = row0 + r;
        float4 v = make_float4(0.f, 0.f, 0.f, 0.f);
        if (gr < NN) v = ((const float4*)(in + (size_t)gr * in_stride))[kq];
        ((float4*)(sh_h + r * K))[kq] = v;
    }
    __syncthreads();

    const int tx = tid & 15, ty = tid >> 4;
    const int c0 = tx * 4, r0 = ty * 4;

    float accl[4][4] = {}, accs[4][4] = {};
#pragma unroll 8
    for (int k = 0; k < K; k++) {
        const float4 wlv = ((const float4*)(sh_wl + k * 64))[tx];
        const float4 wsv = ((const float4*)(sh_ws + k * 64))[tx];
        float h[4];
#pragma unroll
        for (int j = 0; j < 4; j++) h[j] = sh_h[(r0 + j) * K + k];
#pragma unroll
        for (int j = 0; j < 4; j++) {
            accl[j][0] += h[j] * wlv.x; accl[j][1] += h[j] * wlv.y;
            accl[j][2] += h[j] * wlv.z; accl[j][3] += h[j] * wlv.w;
            accs[j][0] += h[j] * wsv.x; accs[j][1] += h[j] * wsv.y;
            accs[j][2] += h[j] * wsv.z; accs[j][3] += h[j] * wsv.w;
        }
    }

    float4 bt;
    bt.x = bl[c0+0] + bs[c0+0] + bias[c0+0];
    bt.y = bl[c0+1] + bs[c0+1] + bias[c0+1];
    bt.z = bl[c0+2] + bs[c0+2] + bias[c0+2];
    bt.w = bl[c0+3] + bs[c0+3] + bias[c0+3];

#pragma unroll
    for (int j = 0; j < 4; j++) {
        int gr = row0 + r0 + j;
        if (gr < NN) {
            __half2 p0 = __floats2half2_rn(accl[j][0], accl[j][1]);
            __half2 p1 = __floats2half2_rn(accl[j][2], accl[j][3]);
            uint2 u = make_uint2(*(unsigned*)&p0, *(unsigned*)&p1);
            ((uint2*)(g_ylin_h + gr * 64))[tx] = u;
            float4 hp = make_float4(accs[j][0] + bt.x, accs[j][1] + bt.y,
                                    accs[j][2] + bt.z, accs[j][3] + bt.w);
            ((float4*)(g_hpre + gr * 64))[tx] = hp;
        }
    }
}

// ============================================================================
// Gather aggregation + relu + store into hcat slice.
// 8 threads per node, each owns 8 halves (one uint4). Edge loop unrolled x4
// for MLP=4. No atomics.
// ============================================================================
__device__ __forceinline__ void acc8(float* acc, uint4 u)
{
    float2 f;
    f = __half22float2(*(__half2*)&u.x); acc[0] += f.x; acc[1] += f.y;
    f = __half22float2(*(__half2*)&u.y); acc[2] += f.x; acc[3] += f.y;
    f = __half22float2(*(__half2*)&u.z); acc[4] += f.x; acc[5] += f.y;
    f = __half22float2(*(__half2*)&u.w); acc[6] += f.x; acc[7] += f.y;
}

__global__ void gather_relu(int layer)
{
    const int t = blockIdx.x * 256 + threadIdx.x;
    const int v = t >> 3;
    const int q = t & 7;
    if (v >= NN) return;
    const int beg = g_rowptr[v];
    const int end = g_rowptr[v + 1];

    const uint4* base = (const uint4*)g_ylin_h;   // 8 uint4 per node row
    float acc[8] = {};

    int e = beg;
    for (; e + 4 <= end; e += 4) {
        int s0 = g_csr_src[e + 0];
        int s1 = g_csr_src[e + 1];
        int s2 = g_csr_src[e + 2];
        int s3 = g_csr_src[e + 3];
        uint4 a = base[s0 * 8 + q];
        uint4 b = base[s1 * 8 + q];
        uint4 c = base[s2 * 8 + q];
        uint4 d = base[s3 * 8 + q];
        acc8(acc, a); acc8(acc, b); acc8(acc, c); acc8(acc, d);
    }
    for (; e < end; e++) {
        int s = g_csr_src[e];
        acc8(acc, base[s * 8 + q]);
    }

    const float4 hp0 = *(const float4*)(g_hpre + v * 64 + q * 8);
    const float4 hp1 = *(const float4*)(g_hpre + v * 64 + q * 8 + 4);
    float* outp = g_hcat + (size_t)v * HCATW + layer * UNITS + q * 8;
    float4 o0, o1;
    o0.x = fmaxf(hp0.x + acc[0], 0.f);
    o0.y = fmaxf(hp0.y + acc[1], 0.f);
    o0.z = fmaxf(hp0.z + acc[2], 0.f);
    o0.w = fmaxf(hp0.w + acc[3], 0.f);
    o1.x = fmaxf(hp1.x + acc[4], 0.f);
    o1.y = fmaxf(hp1.y + acc[5], 0.f);
    o1.z = fmaxf(hp1.z + acc[6], 0.f);
    o1.w = fmaxf(hp1.w + acc[7], 0.f);
    *(float4*)(outp)     = o0;
    *(float4*)(outp + 4) = o1;
}

// ============================================================================
// Final: out = hcat @ w_last + b_last   [NN,384] @ [384,40]
// ============================================================================
__global__ void gemm_last(const float* __restrict__ w, const float* __restrict__ b,
                          float* __restrict__ out)
{
    extern __shared__ float sm[];
    float* sh_w = sm;                  // [384][40]
    float* sh_h = sm + HCATW * OUTF;   // [64][64]

    const int tid = threadIdx.x;       // 0..159
    for (int i = tid; i < HCATW * OUTF / 4; i += 160)
        ((float4*)sh_w)[i] = ((const float4*)w)[i];

    const int row0 = blockIdx.x * 64;
    const int tx = tid % 10, ty = tid / 10;
    const int c0 = tx * 4, r0 = ty * 4;
    float acc[4][4] = {};

    for (int kt = 0; kt < HCATW / 64; kt++) {
        __syncthreads();
        for (int i = tid; i < 64 * 16; i += 160) {
            int r = i / 16, kq = i % 16;
            int gr = row0 + r;
            float4 v = make_float4(0.f, 0.f, 0.f, 0.f);
            if (gr < NN) v = *(const float4*)(g_hcat + (size_t)gr * HCATW + kt * 64 + kq * 4);
            ((float4*)(sh_h + r * 64))[kq] = v;
        }
        __syncthreads();
#pragma unroll 8
        for (int kk = 0; kk < 64; kk++) {
            const int k = kt * 64 + kk;
            const float4 wv = ((const float4*)(sh_w + k * OUTF))[tx];
            float h[4];
#pragma unroll
            for (int j = 0; j < 4; j++) h[j] = sh_h[(r0 + j) * 64 + kk];
#pragma unroll
            for (int j = 0; j < 4; j++) {
                acc[j][0] += h[j] * wv.x; acc[j][1] += h[j] * wv.y;
                acc[j][2] += h[j] * wv.z; acc[j][3] += h[j] * wv.w;
            }
        }
    }

    float4 bv = *(const float4*)(b + c0);
#pragma unroll
    for (int j = 0; j < 4; j++) {
        int gr = row0 + r0 + j;
        if (gr < NN) {
            float4 o = make_float4(acc[j][0] + bv.x, acc[j][1] + bv.y,
                                   acc[j][2] + bv.z, acc[j][3] + bv.w);
            *(float4*)(out + (size_t)gr * OUTF + c0) = o;
        }
    }
}

// ============================================================================
extern "C" void kernel_launch(void* const* d_in, const int* in_sizes, int n_in,
                              void* d_out, int out_size)
{
    const float* x      = (const float*)d_in[0];
    const int*   src    = (const int*)  d_in[1];
    const int*   dst    = (const int*)  d_in[2];
    const float* w0l    = (const float*)d_in[3];
    const float* b0l    = (const float*)d_in[4];
    const float* w0s    = (const float*)d_in[5];
    const float* b0s    = (const float*)d_in[6];
    const float* bias0  = (const float*)d_in[7];
    const float* w_lin  = (const float*)d_in[8];
    const float* b_lin  = (const float*)d_in[9];
    const float* w_self = (const float*)d_in[10];
    const float* b_self = (const float*)d_in[11];
    const float* bias   = (const float*)d_in[12];
    const float* w_last = (const float*)d_in[13];
    const float* b_last = (const float*)d_in[14];
    float* out = (float*)d_out;

    const int SMEM0 = (2 * INF * 64 + 64 * INF) * 4;            // 98304
    const int SMEM1 = (2 * 64 * 64 + 64 * 64) * 4;              // 49152
    const int SMEML = (HCATW * OUTF + 64 * 64) * 4;             // 77824

    cudaFuncSetAttribute((const void*)gemm_dual<INF>,
                         cudaFuncAttributeMaxDynamicSharedMemorySize, SMEM0);
    cudaFuncSetAttribute((const void*)gemm_dual<64>,
                         cudaFuncAttributeMaxDynamicSharedMemorySize, SMEM1);
    cudaFuncSetAttribute((const void*)gemm_last,
                         cudaFuncAttributeMaxDynamicSharedMemorySize, SMEML);

    void* hcat_p = nullptr;
    cudaGetSymbolAddress(&hcat_p, g_hcat);
    const float* hcat = (const float*)hcat_p;

    const int nblk     = (NN + 63) / 64;            // 782
    const int eblk     = (NE + 255) / 256;          // 6250
    const int nodeblk  = (NN + 255) / 256;          // 196
    const int gathblk  = (NN * 8 + 255) / 256;      // 1563

    // ---- CSR build (once per launch) ----
    zero_deg<<<nodeblk, 256>>>();
    hist_deg<<<eblk, 256>>>(dst);
    scan_csr<<<1, 1024>>>();
    fill_csr<<<eblk, 256>>>(src, dst);

    // ---- Layer 0 (input x, K=128) ----
    gemm_dual<INF><<<nblk, 256, SMEM0>>>(x, INF, w0l, w0s, b0l, b0s, bias0);
    gather_relu<<<gathblk, 256>>>(0);

    // ---- Layers 1..5 ----
    for (int l = 1; l < NL; l++) {
        const float* in = hcat + (l - 1) * UNITS;
        const float* wl = w_lin  + (l - 1) * 64 * 64;
        const float* bl = b_lin  + (l - 1) * 64;
        const float* ws = w_self + (l - 1) * 64 * 64;
        const float* bs = b_self + (l - 1) * 64;
        const float* bi = bias   + (l - 1) * 64;
        gemm_dual<64><<<nblk, 256, SMEM1>>>(in, HCATW, wl, ws, bl, bs, bi);
        gather_relu<<<gathblk, 256>>>(l);
    }

    // ---- Final projection ----
    gemm_last<<<nblk, 160, SMEML>>>(w_last, b_last, out);
}